// round 13
// baseline (speedup 1.0000x reference)
#include <cuda_runtime.h>
#include <math.h>

#define BB 2
#define PP 19248
#define NN 100
#define KK 20
#define HG 32
#define HP 138
#define WP 138
#define HH 550
#define WW 550
#define DM 32
#define TI 8
#define NT 13             // ceil(NN/TI)
#define NTP (NT*(NT+1)/2) // 91 tile pairs (ti<=tj)
#define NPIX (HH * WW)    // 302500
#define NPIX4 (NPIX / 4)  // 75625
#define GRID 296          // mega-kernel grid (all co-resident; see launch_bounds proof)
#define FPIX (BB * HP * WP)

// ---------------- scratch (device globals; no allocation allowed) ----------------
__device__ int      g_sIdx[BB][NN];
__device__ float    g_sConf[BB][NN];
__device__ float    g_sLoc[BB][NN][4];
__device__ float    g_ex[BB][NN][HG];       // exp(-.5*dx^2) row factors
__device__ float    g_ey[BB][NN][HG];       // exp(-.5*dy^2) col factors
__device__ float    g_gsum[BB][NN];
__device__ float    g_iou[BB][NN][NN];      // only upper triangle (i<j) written/read
__device__ unsigned g_ioumaxBits[BB][NN];   // float bits of column max (iou >= 0)
__device__ float    g_kConf[BB][KK];
__device__ float    g_kLoc[BB][KK][4];
__device__ __align__(16) float g_kMask[BB][KK][DM];
__device__ float    g_fconf[BB][HP * WP];
__device__ double   g_accum[2];             // [0]=var sum, [1]=ae sum
__device__ int      g_icnt;                 // iou completion counter
__device__ int      g_ready;                // keep/AE done flag
__device__ int      g_fcnt;                 // fconf completion counter
__device__ int      g_vcnt;                 // var completion counter

// ---------------- helpers ----------------
__device__ __forceinline__ float blockReduceSum(float v, float* sm) {
    int lane = threadIdx.x & 31, warp = threadIdx.x >> 5;
#pragma unroll
    for (int o = 16; o; o >>= 1) v += __shfl_down_sync(0xffffffffu, v, o);
    if (lane == 0) sm[warp] = v;
    __syncthreads();
    int nw = (blockDim.x + 31) >> 5;
    v = (threadIdx.x < nw) ? sm[threadIdx.x] : 0.f;
    if (warp == 0) {
#pragma unroll
        for (int o = 16; o; o >>= 1) v += __shfl_down_sync(0xffffffffu, v, o);
    }
    return v;  // valid in thread 0
}

// ---------------- kernel 1: softmax + exact top-100 (radix select) + separable gaussian factors ----------------
__global__ void k_topk(const float* __restrict__ conf, const float* __restrict__ loc) {
    extern __shared__ float vals[];            // PP floats
    __shared__ int hist[256];
    __shared__ int s_bin, s_need;
    __shared__ unsigned long long cand[256];
    __shared__ int s_cnt;
    __shared__ float s_loc4[NN][4];
    __shared__ float s_sx[NN], s_sy[NN];
    int b = blockIdx.x, t = threadIdx.x;
    int lane = t & 31;

    const float2* cb = (const float2*)(conf + (size_t)b * PP * 2);
    for (int i = t; i < PP; i += 1024) {
        float2 c = cb[i];
        float m = fmaxf(c.x, c.y);
        float e0 = expf(c.x - m), e1 = expf(c.y - m);
        vals[i] = e1 / (e0 + e1);              // softmax(...)[:,1] in (0,1)
    }
    if (b == 0 && t < 2) g_accum[t] = 0.0;
    if (b == 0 && t == 2) g_vcnt = 0;
    if (b == 0 && t == 3) g_icnt = 0;
    if (b == 0 && t == 4) g_ready = 0;
    if (b == 0 && t == 5) g_fcnt = 0;
    if (t < NN) g_ioumaxBits[b][t] = 0u;       // reset every replay
    __syncthreads();

    // 3 radix passes on the positive-float bit pattern (monotone in value)
    unsigned prefix = 0;
    int need = NN;
    for (int pass = 0; pass < 3; pass++) {
        int shift = 24 - 8 * pass;
        if (t < 256) hist[t] = 0;
        __syncthreads();
        for (int i = t; i < PP; i += 1024) {
            unsigned bv = __float_as_uint(vals[i]);
            bool ok = (pass == 0) || ((bv >> (shift + 8)) == prefix);
            if (ok) atomicAdd(&hist[(bv >> shift) & 0xFF], 1);
        }
        __syncthreads();
        if (t == 0) {
            int cum = 0, bin = 0;
            for (int q = 255; q >= 0; q--) {
                cum += hist[q];
                if (cum >= need) { bin = q; break; }
            }
            s_bin = bin;
            s_need = need - (cum - hist[bin]);  // remaining quota inside this bin
        }
        __syncthreads();
        prefix = (prefix << 8) | (unsigned)s_bin;
        need = s_need;
        __syncthreads();
    }
    unsigned thr = prefix << 8;                 // lower bound of final bin

    // collect candidates (>= thr)
    if (t == 0) s_cnt = 0;
    __syncthreads();
    for (int i = t; i < PP; i += 1024) {
        unsigned bv = __float_as_uint(vals[i]);
        if (bv >= thr) {
            int p = atomicAdd(&s_cnt, 1);
            if (p < 256)
                cand[p] = ((unsigned long long)bv << 32) | (unsigned)(~i);
        }
    }
    __syncthreads();
    if (t < 256 && t >= s_cnt) cand[t] = 0ULL;
    __syncthreads();

    // bitonic sort 256 keys, descending
    for (int k = 2; k <= 256; k <<= 1) {
        for (int j = k >> 1; j > 0; j >>= 1) {
            if (t < 256) {
                int ixj = t ^ j;
                if (ixj > t) {
                    unsigned long long a = cand[t], c = cand[ixj];
                    bool up = ((t & k) == 0);   // descending in "up" segments
                    if (up ? (a < c) : (a > c)) { cand[t] = c; cand[ixj] = a; }
                }
            }
            __syncthreads();
        }
    }

    if (t < NN) {
        unsigned long long key = cand[t];
        g_sConf[b][t] = __uint_as_float((unsigned)(key >> 32));
        g_sIdx[b][t] = (int)(~(unsigned)key);
    }
    const float* lb = loc + (size_t)b * PP * 4;
    if (t < NN * 4) {
        int r = t >> 2, c = t & 3;
        int idx = (int)(~(unsigned)cand[r]);
        float v = lb[(size_t)idx * 4 + c];
        g_sLoc[b][r][c] = v;
        s_loc4[r][c] = v;
    }
    __syncthreads();

    // separable gaussian factors
    for (int base = 0; base < NN * HG; base += 1024) {
        int item = base + t, k = item >> 5, l2 = item & 31;
        float v = 0.f;
        if (k < NN) {
            float fx = (l2 + 0.5f) / (float)HG;
            float dx = (fx - s_loc4[k][0]) / (s_loc4[k][2] + 1e-4f);
            v = expf(-0.5f * dx * dx);
            g_ex[b][k][l2] = v;
        }
        float s = v;
#pragma unroll
        for (int o = 16; o; o >>= 1) s += __shfl_down_sync(0xffffffffu, s, o);
        if (lane == 0 && k < NN) s_sx[k] = s;
    }
    for (int base = 0; base < NN * HG; base += 1024) {
        int item = base + t, k = item >> 5, l2 = item & 31;
        float v = 0.f;
        if (k < NN) {
            float fy = (l2 + 0.5f) / (float)HG;
            float dy = (fy - s_loc4[k][1]) / (s_loc4[k][3] + 1e-4f);
            v = expf(-0.5f * dy * dy);
            g_ey[b][k][l2] = v;
        }
        float s = v;
#pragma unroll
        for (int o = 16; o; o >>= 1) s += __shfl_down_sync(0xffffffffu, s, o);
        if (lane == 0 && k < NN) s_sy[k] = s;
    }
    __syncthreads();
    if (t < NN) g_gsum[b][t] = s_sx[t] * s_sy[t];
}

// ---------------- kernel 2: MEGA — iou+keep -> fconf -> var, cheap-poll phase sync ----------------
// 296 blocks x 256 threads, all co-resident (launch_bounds(256,4): regs<=64,
// smem ~35KB -> >=4 blocks/SM possible by smem (228/35=6), threads 8/SM; 148*4=592 >= 296).
// Polls use VOLATILE LOADS (no L2 RMW serialization); writers use atomics + threadfence.
__global__ void __launch_bounds__(256, 4)
k_mega(const float* __restrict__ mask, const float* __restrict__ proto,
       const float* __restrict__ orig, float* __restrict__ out) {
    // iou phase smem
    __shared__ float s_exi[TI][HG], s_eyi[TI][HG], s_exj[TI][HG], s_eyj[TI][HG];
    __shared__ float s_gi[TI], s_gj[TI];
    __shared__ bool amLast;
    // keep phase smem
    __shared__ float ioumax[NN];
    __shared__ float sconf[NN];
    __shared__ int keep_s[KK];
    __shared__ float rs_s[KK];
    __shared__ float aepart[KK];
    // fconf phase smem (both batches) — float4-accessed, must be 16B aligned
    __shared__ __align__(16) float sm_mask[BB][KK][DM];
    __shared__ float s_cx[BB][KK], s_cy[BB][KK], s_iw[BB][KK], s_ih[BB][KK], s_cf[BB][KK];
    // var phase: orig staging (hoisted above the grid barrier) + reduce smem
    __shared__ __align__(16) float4 s_ov[256][6];   // 24 KB
    __shared__ float sm[32];

    int bid = blockIdx.x, t = threadIdx.x;
    int w = t >> 5, l = t & 31;

    // ================= phase 1: IoU tiles =================
    if (bid < NTP * BB) {
        int b = bid / NTP;
        int tp = bid % NTP, ti = 0;
        while (tp >= NT - ti) { tp -= NT - ti; ti++; }
        int tj = ti + tp;

        for (int q = t; q < TI * HG; q += 256) {
            int r = q >> 5, c = q & 31;
            int gi = ti * TI + r, gj = tj * TI + r;
            s_exi[r][c] = (gi < NN) ? g_ex[b][gi][c] : 0.f;
            s_eyi[r][c] = (gi < NN) ? g_ey[b][gi][c] : 0.f;
            s_exj[r][c] = (gj < NN) ? g_ex[b][gj][c] : 0.f;
            s_eyj[r][c] = (gj < NN) ? g_ey[b][gj][c] : 0.f;
        }
        if (t < TI) {
            int gi = ti * TI + t, gj = tj * TI + t;
            s_gi[t] = (gi < NN) ? g_gsum[b][gi] : 0.f;
            s_gj[t] = (gj < NN) ? g_gsum[b][gj] : 0.f;
        }
        __syncthreads();

        int i = ti * TI + w;
        float exi_l = s_exi[w][l];
        float exj_r[TI], acc[TI];
#pragma unroll
        for (int jj = 0; jj < TI; jj++) { exj_r[jj] = s_exj[jj][l]; acc[jj] = 0.f; }
        for (int y = 0; y < HG; y++) {
            float a = s_eyi[w][y] * exi_l;
#pragma unroll
            for (int jj = 0; jj < TI; jj++) {
                float bm = s_eyj[jj][y] * exj_r[jj];
                acc[jj] += fminf(a, bm);
            }
        }
#pragma unroll
        for (int jj = 0; jj < TI; jj++) {
            float s = acc[jj];
#pragma unroll
            for (int o = 16; o; o >>= 1) s += __shfl_down_sync(0xffffffffu, s, o);
            int j = tj * TI + jj;
            if (l == 0 && i < NN && j < NN && i < j) {
                float u = s_gi[w] + s_gj[jj] - s;
                float iouv = s / u;
                g_iou[b][i][j] = iouv;
                atomicMax(&g_ioumaxBits[b][j], __float_as_uint(iouv));
            }
        }

        __threadfence();
        __syncthreads();
        if (t == 0) {
            int ticket = atomicAdd(&g_icnt, 1);
            amLast = (ticket == NTP * BB - 1);
        }
        __syncthreads();

        // last iou block: keep + AE for both batches, then release everyone
        if (amLast) {
            for (int bb = 0; bb < BB; bb++) {
                if (t < NN) {
                    ioumax[t] = __uint_as_float(g_ioumaxBits[bb][t]);
                    sconf[t] = g_sConf[bb][t];
                }
                __syncthreads();
                if (t < 32) {
                    for (int r = 0; r < KK; r++) {
                        unsigned long long best = ~0ULL;
                        for (int j = t; j < NN; j += 32) {
                            unsigned long long key =
                                ((unsigned long long)__float_as_uint(ioumax[j]) << 32) | (unsigned)j;
                            if (key < best) best = key;
                        }
#pragma unroll
                        for (int o = 16; o; o >>= 1) {
                            unsigned long long x = __shfl_down_sync(0xffffffffu, best, o);
                            if (x < best) best = x;
                        }
                        best = __shfl_sync(0xffffffffu, best, 0);
                        int j = (int)(unsigned)best;
                        if (t == 0) { keep_s[r] = j; ioumax[j] = 3.4e38f; }
                        __syncwarp();
                    }
                }
                __syncthreads();

                if (t < KK) g_kConf[bb][t] = sconf[keep_s[t]];
                if (t < KK * 4) {
                    int k = t >> 2, c = t & 3;
                    g_kLoc[bb][k][c] = g_sLoc[bb][keep_s[k]][c];
                }
                for (int q = t; q < KK * DM; q += 256) {
                    int k = q >> 5, d = q & (DM - 1);
                    int oi = g_sIdx[bb][keep_s[k]];
                    g_kMask[bb][k][d] = mask[((size_t)bb * PP + oi) * DM + d];
                }
                __syncthreads();

                for (int k = w; k < KK; k += 8) {
                    int i2 = keep_s[k];
                    float s = 0.f;
                    for (int j = i2 + 1 + l; j < NN; j += 32) s += g_iou[bb][i2][j] * sconf[j];
#pragma unroll
                    for (int o = 16; o; o >>= 1) s += __shfl_down_sync(0xffffffffu, s, o);
                    if (l == 0) rs_s[k] = s;
                }
                __syncthreads();

                if (t < KK) {
                    int i2 = keep_s[t];
                    float al = 0.f;
#pragma unroll
                    for (int c = 0; c < 4; c++) {
                        float v = g_kLoc[bb][t][c];
                        al += v * v;
                    }
                    al *= 0.25f;
                    aepart[t] = al * sconf[i2] * rs_s[t];
                }
                __syncthreads();
                if (t == 0) {
                    double s = 0.0;
                    for (int k = 0; k < KK; k++) s += (double)aepart[k];
                    atomicAdd(&g_accum[1], s);
                }
                __syncthreads();
            }
            __threadfence();
            if (t == 0) atomicExch(&g_ready, 1);
        }
    }

    // ================= wait: keep done (volatile-load poll, no RMW) =================
    if (t == 0) {
        while (*((volatile int*)&g_ready) == 0) __nanosleep(256);
    }
    __syncthreads();
    __threadfence();

    // ================= phase 2: fconf over both batches =================
    for (int q = t; q < BB * KK * DM; q += 256) {
        int bb = q / (KK * DM), rem = q % (KK * DM);
        sm_mask[bb][rem >> 5][rem & 31] = g_kMask[bb][rem >> 5][rem & 31];
    }
    if (t < BB * KK) {
        int bb = t / KK, k = t % KK;
        s_cx[bb][k] = g_kLoc[bb][k][0];
        s_cy[bb][k] = g_kLoc[bb][k][1];
        s_iw[bb][k] = 1.f / (g_kLoc[bb][k][2] + 1e-4f);
        s_ih[bb][k] = 1.f / (g_kLoc[bb][k][3] + 1e-4f);
        s_cf[bb][k] = g_kConf[bb][k];
    }
    __syncthreads();

    {
        int idx = bid * 256 + t;
        if (idx < FPIX) {
            int b = idx / (HP * WP);
            int pix = idx - b * (HP * WP);
            int y = pix / WP, x = pix - y * WP;

            const float4* pp = (const float4*)(proto + ((size_t)b * HP * WP + pix) * DM);
            float pr[DM];
#pragma unroll
            for (int q = 0; q < DM / 4; q++) {
                float4 v = pp[q];
                pr[4 * q] = v.x; pr[4 * q + 1] = v.y; pr[4 * q + 2] = v.z; pr[4 * q + 3] = v.w;
            }
            float px_ = (x + 0.5f) / (float)WP, py_ = (y + 0.5f) / (float)HP;
            float s1 = 0.f, s2 = 0.f;
#pragma unroll 2
            for (int k = 0; k < KK; k++) {
                const float4* mk = (const float4*)sm_mask[b][k];
                float d0 = 0.f, d1 = 0.f, d2 = 0.f, d3 = 0.f;
#pragma unroll
                for (int q = 0; q < DM / 4; q++) {
                    float4 mv = mk[q];
                    d0 = fmaf(pr[4 * q], mv.x, d0);
                    d1 = fmaf(pr[4 * q + 1], mv.y, d1);
                    d2 = fmaf(pr[4 * q + 2], mv.z, d2);
                    d3 = fmaf(pr[4 * q + 3], mv.w, d3);
                }
                float dot = (d0 + d1) + (d2 + d3);
                float a = __fdividef(1.f, 1.f + __expf(-dot));
                float dx = (px_ - s_cx[b][k]) * s_iw[b][k];
                float dy = (py_ - s_cy[b][k]) * s_ih[b][k];
                float ug = __expf(-0.5f * fmaf(dx, dx, dy * dy));
                float mc = a * ug * s_cf[b][k];
                s1 += mc;
                s2 = fmaf(mc, mc, s2);
            }
            float fc = 1.f - __fdividef(s2, s1 + 1e-6f);
            if (isnan(fc)) fc = 0.f;
            g_fconf[b][pix] = fc;
        }
    }

    // hoist var-phase DRAM loads ABOVE the grid barrier (overlap wait with DRAM)
    {
        int p4 = bid * 256 + t;
        if (p4 < NPIX4) {
#pragma unroll
            for (int b2 = 0; b2 < 2; b2++)
#pragma unroll
                for (int c = 0; c < 3; c++)
                    s_ov[t][b2 * 3 + c] = ((const float4*)orig)[(size_t)(b2 * 3 + c) * NPIX4 + p4];
        }
    }

    // ================= wait: all fconf done (atomic arrive, volatile poll) =================
    __syncthreads();
    if (t == 0) {
        __threadfence();
        atomicAdd(&g_fcnt, 1);
        while (*((volatile int*)&g_fcnt) < GRID) __nanosleep(256);
    }
    __syncthreads();
    __threadfence();

    // ================= phase 3: bilinear resize + weighted variance + finalize =================
    {
        int p4 = bid * 256 + t;
        float local = 0.f;
        if (p4 < NPIX4) {
            int base = p4 * 4;
#pragma unroll
            for (int e = 0; e < 4; e++) {
                int pix = base + e;
                int h = pix / WW, ww2 = pix - h * WW;
                const float scale = (float)HP / (float)HH;
                float sx = (ww2 + 0.5f) * scale - 0.5f;
                float sy = (h + 0.5f) * scale - 0.5f;
                float fx0 = floorf(sx), fy0 = floorf(sy);
                float ax = sx - fx0, ay = sy - fy0;
                int x0 = min(max((int)fx0, 0), WP - 1);
                int x1 = min(max((int)fx0 + 1, 0), WP - 1);
                int y0 = min(max((int)fy0, 0), HP - 1);
                int y1 = min(max((int)fy0 + 1, 0), HP - 1);
                float w00 = (1.f - ax) * (1.f - ay), w01 = ax * (1.f - ay);
                float w10 = (1.f - ax) * ay, w11 = ax * ay;

                float r0 = g_fconf[0][y0 * WP + x0] * w00 + g_fconf[0][y0 * WP + x1] * w01 +
                           g_fconf[0][y1 * WP + x0] * w10 + g_fconf[0][y1 * WP + x1] * w11;
                float r1 = g_fconf[1][y0 * WP + x0] * w00 + g_fconf[1][y0 * WP + x1] * w01 +
                           g_fconf[1][y1 * WP + x0] * w10 + g_fconf[1][y1 * WP + x1] * w11;
                float total = r0 + r1;
                float invT = __fdividef(1.f, total);
                float invTe = __fdividef(1.f, total + 1e-6f);
#pragma unroll
                for (int c = 0; c < 3; c++) {
                    float o0 = ((const float*)&s_ov[t][0 * 3 + c])[e];
                    float o1 = ((const float*)&s_ov[t][1 * 3 + c])[e];
                    float wm = (o0 * r0 + o1 * r1) * invT;
                    float dd0 = o0 - wm, dd1 = o1 - wm;
                    local += (dd0 * dd0 * r0 + dd1 * dd1 * r1) * invTe;
                }
            }
        }
        float s = blockReduceSum(local, sm);
        if (t == 0) {
            atomicAdd(&g_accum[0], (double)s);
            __threadfence();
            int ticket = atomicAdd(&g_vcnt, 1);
            if (ticket == GRID - 1) {           // last block finalizes
                double v = atomicAdd(&g_accum[0], 0.0);
                double a = atomicAdd(&g_accum[1], 0.0);
                out[0] = (float)(v / (double)HP * (double)BB);
                out[1] = (float)(a / (double)(BB * NN * NN));
            }
        }
    }
}

// ---------------- launch ----------------
extern "C" void kernel_launch(void* const* d_in, const int* in_sizes, int n_in,
                              void* d_out, int out_size) {
    const float *orig = nullptr, *loc = nullptr, *conf = nullptr, *mask = nullptr, *proto = nullptr;
    for (int i = 0; i < n_in; i++) {
        switch (in_sizes[i]) {
            case BB * 3 * HH * WW:   orig  = (const float*)d_in[i]; break;
            case BB * PP * 4:        loc   = (const float*)d_in[i]; break;
            case BB * PP * 2:        conf  = (const float*)d_in[i]; break;
            case BB * PP * DM:       mask  = (const float*)d_in[i]; break;
            case BB * HP * WP * DM:  proto = (const float*)d_in[i]; break;
            default: break;
        }
    }
    if (!orig || !loc || !conf || !mask || !proto) return;

    cudaFuncSetAttribute(k_topk, cudaFuncAttributeMaxDynamicSharedMemorySize, PP * sizeof(float));

    k_topk<<<BB, 1024, PP * sizeof(float)>>>(conf, loc);
    k_mega<<<GRID, 256>>>(mask, proto, orig, (float*)d_out);
}

// round 14
// speedup vs baseline: 1.0171x; 1.0171x over previous
#include <cuda_runtime.h>
#include <math.h>

#define BB 2
#define PP 19248
#define NN 100
#define KK 20
#define HG 32
#define HP 138
#define WP 138
#define HH 550
#define WW 550
#define DM 32
#define TI 8
#define NT 13             // ceil(NN/TI)
#define NTP (NT*(NT+1)/2) // 91 tile pairs (ti<=tj)
#define NPIX (HH * WW)    // 302500
#define NPIX4 (NPIX / 4)  // 75625
#define GRID 296          // = 148 SMs x 2 blocks: all co-resident under launch_bounds(256,2)
#define FPIX (BB * HP * WP)

// ---------------- scratch (device globals; no allocation allowed) ----------------
__device__ int      g_sIdx[BB][NN];
__device__ float    g_sConf[BB][NN];
__device__ float    g_sLoc[BB][NN][4];
__device__ float    g_ex[BB][NN][HG];       // exp(-.5*dx^2) row factors
__device__ float    g_ey[BB][NN][HG];       // exp(-.5*dy^2) col factors
__device__ float    g_gsum[BB][NN];
__device__ float    g_iou[BB][NN][NN];      // only upper triangle (i<j) written/read
__device__ unsigned g_ioumaxBits[BB][NN];   // float bits of column max (iou >= 0)
__device__ float    g_kConf[BB][KK];
__device__ float    g_kLoc[BB][KK][4];
__device__ __align__(16) float g_kMask[BB][KK][DM];
__device__ float    g_fconf[BB][HP * WP];
__device__ double   g_accum[2];             // [0]=var sum, [1]=ae sum
__device__ int      g_icnt;                 // iou completion counter
__device__ int      g_ready;                // keep/AE done flag
__device__ int      g_fcnt;                 // fconf completion counter
__device__ int      g_vcnt;                 // var completion counter

// ---------------- helpers ----------------
__device__ __forceinline__ float blockReduceSum(float v, float* sm) {
    int lane = threadIdx.x & 31, warp = threadIdx.x >> 5;
#pragma unroll
    for (int o = 16; o; o >>= 1) v += __shfl_down_sync(0xffffffffu, v, o);
    if (lane == 0) sm[warp] = v;
    __syncthreads();
    int nw = (blockDim.x + 31) >> 5;
    v = (threadIdx.x < nw) ? sm[threadIdx.x] : 0.f;
    if (warp == 0) {
#pragma unroll
        for (int o = 16; o; o >>= 1) v += __shfl_down_sync(0xffffffffu, v, o);
    }
    return v;  // valid in thread 0
}

__device__ __forceinline__ void l2_prefetch(const void* p) {
    asm volatile("prefetch.global.L2 [%0];" :: "l"(p));
}

// ---------------- kernel 1: softmax + exact top-100 (radix select) + separable gaussian factors ----------------
__global__ void k_topk(const float* __restrict__ conf, const float* __restrict__ loc) {
    extern __shared__ float vals[];            // PP floats
    __shared__ int hist[256];
    __shared__ int s_bin, s_need;
    __shared__ unsigned long long cand[256];
    __shared__ int s_cnt;
    __shared__ float s_loc4[NN][4];
    __shared__ float s_sx[NN], s_sy[NN];
    int b = blockIdx.x, t = threadIdx.x;
    int lane = t & 31;

    const float2* cb = (const float2*)(conf + (size_t)b * PP * 2);
    for (int i = t; i < PP; i += 1024) {
        float2 c = cb[i];
        float m = fmaxf(c.x, c.y);
        float e0 = expf(c.x - m), e1 = expf(c.y - m);
        vals[i] = e1 / (e0 + e1);              // softmax(...)[:,1] in (0,1)
    }
    if (b == 0 && t < 2) g_accum[t] = 0.0;
    if (b == 0 && t == 2) g_vcnt = 0;
    if (b == 0 && t == 3) g_icnt = 0;
    if (b == 0 && t == 4) g_ready = 0;
    if (b == 0 && t == 5) g_fcnt = 0;
    if (t < NN) g_ioumaxBits[b][t] = 0u;       // reset every replay
    __syncthreads();

    // 3 radix passes on the positive-float bit pattern (monotone in value)
    unsigned prefix = 0;
    int need = NN;
    for (int pass = 0; pass < 3; pass++) {
        int shift = 24 - 8 * pass;
        if (t < 256) hist[t] = 0;
        __syncthreads();
        for (int i = t; i < PP; i += 1024) {
            unsigned bv = __float_as_uint(vals[i]);
            bool ok = (pass == 0) || ((bv >> (shift + 8)) == prefix);
            if (ok) atomicAdd(&hist[(bv >> shift) & 0xFF], 1);
        }
        __syncthreads();
        if (t == 0) {
            int cum = 0, bin = 0;
            for (int q = 255; q >= 0; q--) {
                cum += hist[q];
                if (cum >= need) { bin = q; break; }
            }
            s_bin = bin;
            s_need = need - (cum - hist[bin]);  // remaining quota inside this bin
        }
        __syncthreads();
        prefix = (prefix << 8) | (unsigned)s_bin;
        need = s_need;
        __syncthreads();
    }
    unsigned thr = prefix << 8;                 // lower bound of final bin

    // collect candidates (>= thr)
    if (t == 0) s_cnt = 0;
    __syncthreads();
    for (int i = t; i < PP; i += 1024) {
        unsigned bv = __float_as_uint(vals[i]);
        if (bv >= thr) {
            int p = atomicAdd(&s_cnt, 1);
            if (p < 256)
                cand[p] = ((unsigned long long)bv << 32) | (unsigned)(~i);
        }
    }
    __syncthreads();
    if (t < 256 && t >= s_cnt) cand[t] = 0ULL;
    __syncthreads();

    // bitonic sort 256 keys, descending
    for (int k = 2; k <= 256; k <<= 1) {
        for (int j = k >> 1; j > 0; j >>= 1) {
            if (t < 256) {
                int ixj = t ^ j;
                if (ixj > t) {
                    unsigned long long a = cand[t], c = cand[ixj];
                    bool up = ((t & k) == 0);   // descending in "up" segments
                    if (up ? (a < c) : (a > c)) { cand[t] = c; cand[ixj] = a; }
                }
            }
            __syncthreads();
        }
    }

    if (t < NN) {
        unsigned long long key = cand[t];
        g_sConf[b][t] = __uint_as_float((unsigned)(key >> 32));
        g_sIdx[b][t] = (int)(~(unsigned)key);
    }
    const float* lb = loc + (size_t)b * PP * 4;
    if (t < NN * 4) {
        int r = t >> 2, c = t & 3;
        int idx = (int)(~(unsigned)cand[r]);
        float v = lb[(size_t)idx * 4 + c];
        g_sLoc[b][r][c] = v;
        s_loc4[r][c] = v;
    }
    __syncthreads();

    // separable gaussian factors
    for (int base = 0; base < NN * HG; base += 1024) {
        int item = base + t, k = item >> 5, l2 = item & 31;
        float v = 0.f;
        if (k < NN) {
            float fx = (l2 + 0.5f) / (float)HG;
            float dx = (fx - s_loc4[k][0]) / (s_loc4[k][2] + 1e-4f);
            v = expf(-0.5f * dx * dx);
            g_ex[b][k][l2] = v;
        }
        float s = v;
#pragma unroll
        for (int o = 16; o; o >>= 1) s += __shfl_down_sync(0xffffffffu, s, o);
        if (lane == 0 && k < NN) s_sx[k] = s;
    }
    for (int base = 0; base < NN * HG; base += 1024) {
        int item = base + t, k = item >> 5, l2 = item & 31;
        float v = 0.f;
        if (k < NN) {
            float fy = (l2 + 0.5f) / (float)HG;
            float dy = (fy - s_loc4[k][1]) / (s_loc4[k][3] + 1e-4f);
            v = expf(-0.5f * dy * dy);
            g_ey[b][k][l2] = v;
        }
        float s = v;
#pragma unroll
        for (int o = 16; o; o >>= 1) s += __shfl_down_sync(0xffffffffu, s, o);
        if (lane == 0 && k < NN) s_sy[k] = s;
    }
    __syncthreads();
    if (t < NN) g_gsum[b][t] = s_sx[t] * s_sy[t];
}

// ---------------- kernel 2: MEGA — iou+keep -> fconf -> var, cheap-poll phase sync ----------------
// 296 blocks x 256 threads = 148 SMs x 2 co-resident blocks (launch_bounds(256,2):
// reg cap 128 -> NO SPILLS of pr[32]/var temporaries; smem 35KB x 2 = 70 <= 228 KB).
__global__ void __launch_bounds__(256, 2)
k_mega(const float* __restrict__ mask, const float* __restrict__ proto,
       const float* __restrict__ orig, float* __restrict__ out) {
    // iou phase smem
    __shared__ float s_exi[TI][HG], s_eyi[TI][HG], s_exj[TI][HG], s_eyj[TI][HG];
    __shared__ float s_gi[TI], s_gj[TI];
    __shared__ bool amLast;
    // keep phase smem
    __shared__ float ioumax[NN];
    __shared__ float sconf[NN];
    __shared__ int keep_s[KK];
    __shared__ float rs_s[KK];
    __shared__ float aepart[KK];
    // fconf phase smem (both batches) — float4-accessed, must be 16B aligned
    __shared__ __align__(16) float sm_mask[BB][KK][DM];
    __shared__ float s_cx[BB][KK], s_cy[BB][KK], s_iw[BB][KK], s_ih[BB][KK], s_cf[BB][KK];
    // var phase: orig staging (hoisted above the grid barrier) + reduce smem
    __shared__ __align__(16) float4 s_ov[256][6];   // 24 KB
    __shared__ float sm[32];

    int bid = blockIdx.x, t = threadIdx.x;
    int w = t >> 5, l = t & 31;

    // ---- warm L2 with proto + orig while iou/keep run (fire-and-forget) ----
    {
        int gtid = bid * 256 + t;
        const int protoLines = (FPIX * DM) / 32;           // 128B lines
        const int origLines  = (BB * 3 * NPIX + 31) / 32;
        for (int ln = gtid; ln < protoLines; ln += GRID * 256)
            l2_prefetch(proto + (size_t)ln * 32);
        for (int ln = gtid; ln < origLines; ln += GRID * 256)
            l2_prefetch(orig + (size_t)ln * 32);
    }

    // ================= phase 1: IoU tiles =================
    if (bid < NTP * BB) {
        int b = bid / NTP;
        int tp = bid % NTP, ti = 0;
        while (tp >= NT - ti) { tp -= NT - ti; ti++; }
        int tj = ti + tp;

        for (int q = t; q < TI * HG; q += 256) {
            int r = q >> 5, c = q & 31;
            int gi = ti * TI + r, gj = tj * TI + r;
            s_exi[r][c] = (gi < NN) ? g_ex[b][gi][c] : 0.f;
            s_eyi[r][c] = (gi < NN) ? g_ey[b][gi][c] : 0.f;
            s_exj[r][c] = (gj < NN) ? g_ex[b][gj][c] : 0.f;
            s_eyj[r][c] = (gj < NN) ? g_ey[b][gj][c] : 0.f;
        }
        if (t < TI) {
            int gi = ti * TI + t, gj = tj * TI + t;
            s_gi[t] = (gi < NN) ? g_gsum[b][gi] : 0.f;
            s_gj[t] = (gj < NN) ? g_gsum[b][gj] : 0.f;
        }
        __syncthreads();

        int i = ti * TI + w;
        float exi_l = s_exi[w][l];
        float exj_r[TI], acc[TI];
#pragma unroll
        for (int jj = 0; jj < TI; jj++) { exj_r[jj] = s_exj[jj][l]; acc[jj] = 0.f; }
        for (int y = 0; y < HG; y++) {
            float a = s_eyi[w][y] * exi_l;
#pragma unroll
            for (int jj = 0; jj < TI; jj++) {
                float bm = s_eyj[jj][y] * exj_r[jj];
                acc[jj] += fminf(a, bm);
            }
        }
#pragma unroll
        for (int jj = 0; jj < TI; jj++) {
            float s = acc[jj];
#pragma unroll
            for (int o = 16; o; o >>= 1) s += __shfl_down_sync(0xffffffffu, s, o);
            int j = tj * TI + jj;
            if (l == 0 && i < NN && j < NN && i < j) {
                float u = s_gi[w] + s_gj[jj] - s;
                float iouv = s / u;
                g_iou[b][i][j] = iouv;
                atomicMax(&g_ioumaxBits[b][j], __float_as_uint(iouv));
            }
        }

        __threadfence();
        __syncthreads();
        if (t == 0) {
            int ticket = atomicAdd(&g_icnt, 1);
            amLast = (ticket == NTP * BB - 1);
        }
        __syncthreads();

        // last iou block: keep + AE for both batches, then release everyone
        if (amLast) {
            for (int bb = 0; bb < BB; bb++) {
                if (t < NN) {
                    ioumax[t] = __uint_as_float(g_ioumaxBits[bb][t]);
                    sconf[t] = g_sConf[bb][t];
                }
                __syncthreads();
                if (t < 32) {
                    for (int r = 0; r < KK; r++) {
                        unsigned long long best = ~0ULL;
                        for (int j = t; j < NN; j += 32) {
                            unsigned long long key =
                                ((unsigned long long)__float_as_uint(ioumax[j]) << 32) | (unsigned)j;
                            if (key < best) best = key;
                        }
#pragma unroll
                        for (int o = 16; o; o >>= 1) {
                            unsigned long long x = __shfl_down_sync(0xffffffffu, best, o);
                            if (x < best) best = x;
                        }
                        best = __shfl_sync(0xffffffffu, best, 0);
                        int j = (int)(unsigned)best;
                        if (t == 0) { keep_s[r] = j; ioumax[j] = 3.4e38f; }
                        __syncwarp();
                    }
                }
                __syncthreads();

                if (t < KK) g_kConf[bb][t] = sconf[keep_s[t]];
                if (t < KK * 4) {
                    int k = t >> 2, c = t & 3;
                    g_kLoc[bb][k][c] = g_sLoc[bb][keep_s[k]][c];
                }
                for (int q = t; q < KK * DM; q += 256) {
                    int k = q >> 5, d = q & (DM - 1);
                    int oi = g_sIdx[bb][keep_s[k]];
                    g_kMask[bb][k][d] = mask[((size_t)bb * PP + oi) * DM + d];
                }
                __syncthreads();

                for (int k = w; k < KK; k += 8) {
                    int i2 = keep_s[k];
                    float s = 0.f;
                    for (int j = i2 + 1 + l; j < NN; j += 32) s += g_iou[bb][i2][j] * sconf[j];
#pragma unroll
                    for (int o = 16; o; o >>= 1) s += __shfl_down_sync(0xffffffffu, s, o);
                    if (l == 0) rs_s[k] = s;
                }
                __syncthreads();

                if (t < KK) {
                    int i2 = keep_s[t];
                    float al = 0.f;
#pragma unroll
                    for (int c = 0; c < 4; c++) {
                        float v = g_kLoc[bb][t][c];
                        al += v * v;
                    }
                    al *= 0.25f;
                    aepart[t] = al * sconf[i2] * rs_s[t];
                }
                __syncthreads();
                if (t == 0) {
                    double s = 0.0;
                    for (int k = 0; k < KK; k++) s += (double)aepart[k];
                    atomicAdd(&g_accum[1], s);
                }
                __syncthreads();
            }
            __threadfence();
            if (t == 0) atomicExch(&g_ready, 1);
        }
    }

    // ================= wait: keep done (volatile-load poll, no RMW) =================
    if (t == 0) {
        while (*((volatile int*)&g_ready) == 0) __nanosleep(256);
    }
    __syncthreads();
    __threadfence();

    // ================= phase 2: fconf over both batches =================
    for (int q = t; q < BB * KK * DM; q += 256) {
        int bb = q / (KK * DM), rem = q % (KK * DM);
        sm_mask[bb][rem >> 5][rem & 31] = g_kMask[bb][rem >> 5][rem & 31];
    }
    if (t < BB * KK) {
        int bb = t / KK, k = t % KK;
        s_cx[bb][k] = g_kLoc[bb][k][0];
        s_cy[bb][k] = g_kLoc[bb][k][1];
        s_iw[bb][k] = 1.f / (g_kLoc[bb][k][2] + 1e-4f);
        s_ih[bb][k] = 1.f / (g_kLoc[bb][k][3] + 1e-4f);
        s_cf[bb][k] = g_kConf[bb][k];
    }
    __syncthreads();

    {
        int idx = bid * 256 + t;
        if (idx < FPIX) {
            int b = idx / (HP * WP);
            int pix = idx - b * (HP * WP);
            int y = pix / WP, x = pix - y * WP;

            const float4* pp = (const float4*)(proto + ((size_t)b * HP * WP + pix) * DM);
            float pr[DM];
#pragma unroll
            for (int q = 0; q < DM / 4; q++) {
                float4 v = pp[q];
                pr[4 * q] = v.x; pr[4 * q + 1] = v.y; pr[4 * q + 2] = v.z; pr[4 * q + 3] = v.w;
            }
            float px_ = (x + 0.5f) / (float)WP, py_ = (y + 0.5f) / (float)HP;
            float s1 = 0.f, s2 = 0.f;
#pragma unroll 2
            for (int k = 0; k < KK; k++) {
                const float4* mk = (const float4*)sm_mask[b][k];
                float d0 = 0.f, d1 = 0.f, d2 = 0.f, d3 = 0.f;
#pragma unroll
                for (int q = 0; q < DM / 4; q++) {
                    float4 mv = mk[q];
                    d0 = fmaf(pr[4 * q], mv.x, d0);
                    d1 = fmaf(pr[4 * q + 1], mv.y, d1);
                    d2 = fmaf(pr[4 * q + 2], mv.z, d2);
                    d3 = fmaf(pr[4 * q + 3], mv.w, d3);
                }
                float dot = (d0 + d1) + (d2 + d3);
                float a = __fdividef(1.f, 1.f + __expf(-dot));
                float dx = (px_ - s_cx[b][k]) * s_iw[b][k];
                float dy = (py_ - s_cy[b][k]) * s_ih[b][k];
                float ug = __expf(-0.5f * fmaf(dx, dx, dy * dy));
                float mc = a * ug * s_cf[b][k];
                s1 += mc;
                s2 = fmaf(mc, mc, s2);
            }
            float fc = 1.f - __fdividef(s2, s1 + 1e-6f);
            if (isnan(fc)) fc = 0.f;
            g_fconf[b][pix] = fc;
        }
    }

    // hoist var-phase DRAM loads ABOVE the grid barrier (overlap wait with memory)
    {
        int p4 = bid * 256 + t;
        if (p4 < NPIX4) {
#pragma unroll
            for (int b2 = 0; b2 < 2; b2++)
#pragma unroll
                for (int c = 0; c < 3; c++)
                    s_ov[t][b2 * 3 + c] = ((const float4*)orig)[(size_t)(b2 * 3 + c) * NPIX4 + p4];
        }
    }

    // ================= wait: all fconf done (atomic arrive, volatile poll) =================
    __syncthreads();
    if (t == 0) {
        __threadfence();
        atomicAdd(&g_fcnt, 1);
        while (*((volatile int*)&g_fcnt) < GRID) __nanosleep(256);
    }
    __syncthreads();
    __threadfence();

    // ================= phase 3: bilinear resize + weighted variance + finalize =================
    {
        int p4 = bid * 256 + t;
        float local = 0.f;
        if (p4 < NPIX4) {
            int base = p4 * 4;
#pragma unroll
            for (int e = 0; e < 4; e++) {
                int pix = base + e;
                int h = pix / WW, ww2 = pix - h * WW;
                const float scale = (float)HP / (float)HH;
                float sx = (ww2 + 0.5f) * scale - 0.5f;
                float sy = (h + 0.5f) * scale - 0.5f;
                float fx0 = floorf(sx), fy0 = floorf(sy);
                float ax = sx - fx0, ay = sy - fy0;
                int x0 = min(max((int)fx0, 0), WP - 1);
                int x1 = min(max((int)fx0 + 1, 0), WP - 1);
                int y0 = min(max((int)fy0, 0), HP - 1);
                int y1 = min(max((int)fy0 + 1, 0), HP - 1);
                float w00 = (1.f - ax) * (1.f - ay), w01 = ax * (1.f - ay);
                float w10 = (1.f - ax) * ay, w11 = ax * ay;

                float r0 = g_fconf[0][y0 * WP + x0] * w00 + g_fconf[0][y0 * WP + x1] * w01 +
                           g_fconf[0][y1 * WP + x0] * w10 + g_fconf[0][y1 * WP + x1] * w11;
                float r1 = g_fconf[1][y0 * WP + x0] * w00 + g_fconf[1][y0 * WP + x1] * w01 +
                           g_fconf[1][y1 * WP + x0] * w10 + g_fconf[1][y1 * WP + x1] * w11;
                float total = r0 + r1;
                float invT = __fdividef(1.f, total);
                float invTe = __fdividef(1.f, total + 1e-6f);
#pragma unroll
                for (int c = 0; c < 3; c++) {
                    float o0 = ((const float*)&s_ov[t][0 * 3 + c])[e];
                    float o1 = ((const float*)&s_ov[t][1 * 3 + c])[e];
                    float wm = (o0 * r0 + o1 * r1) * invT;
                    float dd0 = o0 - wm, dd1 = o1 - wm;
                    local += (dd0 * dd0 * r0 + dd1 * dd1 * r1) * invTe;
                }
            }
        }
        float s = blockReduceSum(local, sm);
        if (t == 0) {
            atomicAdd(&g_accum[0], (double)s);
            __threadfence();
            int ticket = atomicAdd(&g_vcnt, 1);
            if (ticket == GRID - 1) {           // last block finalizes
                double v = atomicAdd(&g_accum[0], 0.0);
                double a = atomicAdd(&g_accum[1], 0.0);
                out[0] = (float)(v / (double)HP * (double)BB);
                out[1] = (float)(a / (double)(BB * NN * NN));
            }
        }
    }
}

// ---------------- launch ----------------
extern "C" void kernel_launch(void* const* d_in, const int* in_sizes, int n_in,
                              void* d_out, int out_size) {
    const float *orig = nullptr, *loc = nullptr, *conf = nullptr, *mask = nullptr, *proto = nullptr;
    for (int i = 0; i < n_in; i++) {
        switch (in_sizes[i]) {
            case BB * 3 * HH * WW:   orig  = (const float*)d_in[i]; break;
            case BB * PP * 4:        loc   = (const float*)d_in[i]; break;
            case BB * PP * 2:        conf  = (const float*)d_in[i]; break;
            case BB * PP * DM:       mask  = (const float*)d_in[i]; break;
            case BB * HP * WP * DM:  proto = (const float*)d_in[i]; break;
            default: break;
        }
    }
    if (!orig || !loc || !conf || !mask || !proto) return;

    cudaFuncSetAttribute(k_topk, cudaFuncAttributeMaxDynamicSharedMemorySize, PP * sizeof(float));

    k_topk<<<BB, 1024, PP * sizeof(float)>>>(conf, loc);
    k_mega<<<GRID, 256>>>(mask, proto, orig, (float*)d_out);
}

// round 15
// speedup vs baseline: 1.0321x; 1.0148x over previous
#include <cuda_runtime.h>
#include <math.h>

#define BB 2
#define PP 19248
#define NN 100
#define KK 20
#define HG 32
#define HP 138
#define WP 138
#define HH 550
#define WW 550
#define DM 32
#define TI 8
#define NT 13             // ceil(NN/TI)
#define NTP (NT*(NT+1)/2) // 91 tile pairs (ti<=tj)
#define NPIX (HH * WW)    // 302500
#define NPIX4 (NPIX / 4)  // 75625
#define GRID 296          // = 148 SMs x 2 blocks: all co-resident under launch_bounds(256,2)
#define FPIX (BB * HP * WP)

// ---------------- scratch (device globals; no allocation allowed) ----------------
__device__ int      g_sIdx[BB][NN];
__device__ float    g_sConf[BB][NN];
__device__ float    g_sLoc[BB][NN][4];
__device__ float    g_ex[BB][NN][HG];       // exp(-.5*dx^2) row factors
__device__ float    g_ey[BB][NN][HG];       // exp(-.5*dy^2) col factors
__device__ float    g_gsum[BB][NN];
__device__ float    g_iou[BB][NN][NN];      // only upper triangle (i<j) written/read
__device__ unsigned g_ioumaxBits[BB][NN];   // float bits of column max (iou >= 0)
__device__ float    g_kConf[BB][KK];
__device__ float    g_kLoc[BB][KK][4];
__device__ __align__(16) float g_kMask[BB][KK][DM];
__device__ float    g_fconf[BB][HP * WP];
__device__ double   g_accum[2];             // [0]=var sum, [1]=ae sum
__device__ int      g_icnt;                 // iou completion counter
__device__ int      g_ready;                // keep/AE done flag
__device__ int      g_fcnt;                 // fconf completion counter
__device__ int      g_vcnt;                 // var completion counter

// ---------------- helpers ----------------
__device__ __forceinline__ float blockReduceSum(float v, float* sm) {
    int lane = threadIdx.x & 31, warp = threadIdx.x >> 5;
#pragma unroll
    for (int o = 16; o; o >>= 1) v += __shfl_down_sync(0xffffffffu, v, o);
    if (lane == 0) sm[warp] = v;
    __syncthreads();
    int nw = (blockDim.x + 31) >> 5;
    v = (threadIdx.x < nw) ? sm[threadIdx.x] : 0.f;
    if (warp == 0) {
#pragma unroll
        for (int o = 16; o; o >>= 1) v += __shfl_down_sync(0xffffffffu, v, o);
    }
    return v;  // valid in thread 0
}

__device__ __forceinline__ void l2_prefetch(const void* p) {
    asm volatile("prefetch.global.L2 [%0];" :: "l"(p));
}

// ---------------- kernel 1: softmax + exact top-100 (radix select) + separable gaussian factors ----------------
__global__ void k_topk(const float* __restrict__ conf, const float* __restrict__ loc) {
    extern __shared__ float vals[];            // PP floats
    __shared__ int hist[256];
    __shared__ int s_bin, s_need;
    __shared__ unsigned long long cand[256];
    __shared__ int s_cnt;
    __shared__ float s_loc4[NN][4];
    __shared__ float s_sx[NN], s_sy[NN];
    int b = blockIdx.x, t = threadIdx.x;
    int lane = t & 31;

    const float2* cb = (const float2*)(conf + (size_t)b * PP * 2);
    for (int i = t; i < PP; i += 1024) {
        float2 c = cb[i];
        // softmax(...)[:,1] == sigmoid(c1 - c0); MUFU fast path (monotone, ~5e-7 rel)
        vals[i] = __fdividef(1.f, 1.f + __expf(c.x - c.y));
    }
    if (b == 0 && t < 2) g_accum[t] = 0.0;
    if (b == 0 && t == 2) g_vcnt = 0;
    if (b == 0 && t == 3) g_icnt = 0;
    if (b == 0 && t == 4) g_ready = 0;
    if (b == 0 && t == 5) g_fcnt = 0;
    if (t < NN) g_ioumaxBits[b][t] = 0u;       // reset every replay
    __syncthreads();

    // 3 radix passes on the positive-float bit pattern (monotone in value)
    unsigned prefix = 0;
    int need = NN;
    for (int pass = 0; pass < 3; pass++) {
        int shift = 24 - 8 * pass;
        if (t < 256) hist[t] = 0;
        __syncthreads();
        for (int i = t; i < PP; i += 1024) {
            unsigned bv = __float_as_uint(vals[i]);
            bool ok = (pass == 0) || ((bv >> (shift + 8)) == prefix);
            if (ok) atomicAdd(&hist[(bv >> shift) & 0xFF], 1);
        }
        __syncthreads();
        if (t == 0) {
            int cum = 0, bin = 0;
            for (int q = 255; q >= 0; q--) {
                cum += hist[q];
                if (cum >= need) { bin = q; break; }
            }
            s_bin = bin;
            s_need = need - (cum - hist[bin]);  // remaining quota inside this bin
        }
        __syncthreads();
        prefix = (prefix << 8) | (unsigned)s_bin;
        need = s_need;
        __syncthreads();
    }
    unsigned thr = prefix << 8;                 // lower bound of final bin

    // collect candidates (>= thr)
    if (t == 0) s_cnt = 0;
    __syncthreads();
    for (int i = t; i < PP; i += 1024) {
        unsigned bv = __float_as_uint(vals[i]);
        if (bv >= thr) {
            int p = atomicAdd(&s_cnt, 1);
            if (p < 256)
                cand[p] = ((unsigned long long)bv << 32) | (unsigned)(~i);
        }
    }
    __syncthreads();
    if (t < 256 && t >= s_cnt) cand[t] = 0ULL;
    __syncthreads();

    // bitonic sort 256 keys, descending
    for (int k = 2; k <= 256; k <<= 1) {
        for (int j = k >> 1; j > 0; j >>= 1) {
            if (t < 256) {
                int ixj = t ^ j;
                if (ixj > t) {
                    unsigned long long a = cand[t], c = cand[ixj];
                    bool up = ((t & k) == 0);   // descending in "up" segments
                    if (up ? (a < c) : (a > c)) { cand[t] = c; cand[ixj] = a; }
                }
            }
            __syncthreads();
        }
    }

    if (t < NN) {
        unsigned long long key = cand[t];
        g_sConf[b][t] = __uint_as_float((unsigned)(key >> 32));
        g_sIdx[b][t] = (int)(~(unsigned)key);
    }
    const float* lb = loc + (size_t)b * PP * 4;
    if (t < NN * 4) {
        int r = t >> 2, c = t & 3;
        int idx = (int)(~(unsigned)cand[r]);
        float v = lb[(size_t)idx * 4 + c];
        g_sLoc[b][r][c] = v;
        s_loc4[r][c] = v;
    }
    __syncthreads();

    // separable gaussian factors (MUFU exp; feeds iou ranking + sums, 1e-3 budget)
    for (int base = 0; base < NN * HG; base += 1024) {
        int item = base + t, k = item >> 5, l2 = item & 31;
        float v = 0.f;
        if (k < NN) {
            float fx = (l2 + 0.5f) / (float)HG;
            float dx = (fx - s_loc4[k][0]) * __fdividef(1.f, s_loc4[k][2] + 1e-4f);
            v = __expf(-0.5f * dx * dx);
            g_ex[b][k][l2] = v;
        }
        float s = v;
#pragma unroll
        for (int o = 16; o; o >>= 1) s += __shfl_down_sync(0xffffffffu, s, o);
        if (lane == 0 && k < NN) s_sx[k] = s;
    }
    for (int base = 0; base < NN * HG; base += 1024) {
        int item = base + t, k = item >> 5, l2 = item & 31;
        float v = 0.f;
        if (k < NN) {
            float fy = (l2 + 0.5f) / (float)HG;
            float dy = (fy - s_loc4[k][1]) * __fdividef(1.f, s_loc4[k][3] + 1e-4f);
            v = __expf(-0.5f * dy * dy);
            g_ey[b][k][l2] = v;
        }
        float s = v;
#pragma unroll
        for (int o = 16; o; o >>= 1) s += __shfl_down_sync(0xffffffffu, s, o);
        if (lane == 0 && k < NN) s_sy[k] = s;
    }
    __syncthreads();
    if (t < NN) g_gsum[b][t] = s_sx[t] * s_sy[t];
}

// ---------------- kernel 2: MEGA — iou+keep -> fconf -> var, pure-spin phase sync ----------------
// 296 blocks x 256 threads = 148 SMs x 2 co-resident blocks (launch_bounds(256,2)).
// Polls are PURE volatile-load spins (no __nanosleep — its multi-us quantum was the
// suspected ~40us tax); deadlock-free because all 296 blocks are wave-1 resident.
__global__ void __launch_bounds__(256, 2)
k_mega(const float* __restrict__ mask, const float* __restrict__ proto,
       const float* __restrict__ orig, float* __restrict__ out) {
    // iou phase smem
    __shared__ float s_exi[TI][HG], s_eyi[TI][HG], s_exj[TI][HG], s_eyj[TI][HG];
    __shared__ float s_gi[TI], s_gj[TI];
    __shared__ bool amLast;
    // keep phase smem
    __shared__ float ioumax[NN];
    __shared__ float sconf[NN];
    __shared__ int keep_s[KK];
    __shared__ float rs_s[KK];
    __shared__ float aepart[KK];
    // fconf phase smem (both batches) — float4-accessed, must be 16B aligned
    __shared__ __align__(16) float sm_mask[BB][KK][DM];
    __shared__ float s_cx[BB][KK], s_cy[BB][KK], s_iw[BB][KK], s_ih[BB][KK], s_cf[BB][KK];
    // var phase: orig staging (hoisted above the grid barrier) + reduce smem
    __shared__ __align__(16) float4 s_ov[256][6];   // 24 KB
    __shared__ float sm[32];

    int bid = blockIdx.x, t = threadIdx.x;
    int w = t >> 5, l = t & 31;

    // ---- warm L2 with proto + orig while iou/keep run (fire-and-forget) ----
    {
        int gtid = bid * 256 + t;
        const int protoLines = (FPIX * DM) / 32;           // 128B lines
        const int origLines  = (BB * 3 * NPIX + 31) / 32;
        for (int ln = gtid; ln < protoLines; ln += GRID * 256)
            l2_prefetch(proto + (size_t)ln * 32);
        for (int ln = gtid; ln < origLines; ln += GRID * 256)
            l2_prefetch(orig + (size_t)ln * 32);
    }

    // ================= phase 1: IoU tiles =================
    if (bid < NTP * BB) {
        int b = bid / NTP;
        int tp = bid % NTP, ti = 0;
        while (tp >= NT - ti) { tp -= NT - ti; ti++; }
        int tj = ti + tp;

        for (int q = t; q < TI * HG; q += 256) {
            int r = q >> 5, c = q & 31;
            int gi = ti * TI + r, gj = tj * TI + r;
            s_exi[r][c] = (gi < NN) ? g_ex[b][gi][c] : 0.f;
            s_eyi[r][c] = (gi < NN) ? g_ey[b][gi][c] : 0.f;
            s_exj[r][c] = (gj < NN) ? g_ex[b][gj][c] : 0.f;
            s_eyj[r][c] = (gj < NN) ? g_ey[b][gj][c] : 0.f;
        }
        if (t < TI) {
            int gi = ti * TI + t, gj = tj * TI + t;
            s_gi[t] = (gi < NN) ? g_gsum[b][gi] : 0.f;
            s_gj[t] = (gj < NN) ? g_gsum[b][gj] : 0.f;
        }
        __syncthreads();

        int i = ti * TI + w;
        float exi_l = s_exi[w][l];
        float exj_r[TI], acc[TI];
#pragma unroll
        for (int jj = 0; jj < TI; jj++) { exj_r[jj] = s_exj[jj][l]; acc[jj] = 0.f; }
        for (int y = 0; y < HG; y++) {
            float a = s_eyi[w][y] * exi_l;
#pragma unroll
            for (int jj = 0; jj < TI; jj++) {
                float bm = s_eyj[jj][y] * exj_r[jj];
                acc[jj] += fminf(a, bm);
            }
        }
#pragma unroll
        for (int jj = 0; jj < TI; jj++) {
            float s = acc[jj];
#pragma unroll
            for (int o = 16; o; o >>= 1) s += __shfl_down_sync(0xffffffffu, s, o);
            int j = tj * TI + jj;
            if (l == 0 && i < NN && j < NN && i < j) {
                float u = s_gi[w] + s_gj[jj] - s;
                float iouv = s / u;
                g_iou[b][i][j] = iouv;
                atomicMax(&g_ioumaxBits[b][j], __float_as_uint(iouv));
            }
        }

        __threadfence();
        __syncthreads();
        if (t == 0) {
            int ticket = atomicAdd(&g_icnt, 1);
            amLast = (ticket == NTP * BB - 1);
        }
        __syncthreads();

        // last iou block: keep + AE for both batches, then release everyone
        if (amLast) {
            for (int bb = 0; bb < BB; bb++) {
                if (t < NN) {
                    ioumax[t] = __uint_as_float(g_ioumaxBits[bb][t]);
                    sconf[t] = g_sConf[bb][t];
                }
                __syncthreads();
                if (t < 32) {
                    for (int r = 0; r < KK; r++) {
                        unsigned long long best = ~0ULL;
                        for (int j = t; j < NN; j += 32) {
                            unsigned long long key =
                                ((unsigned long long)__float_as_uint(ioumax[j]) << 32) | (unsigned)j;
                            if (key < best) best = key;
                        }
#pragma unroll
                        for (int o = 16; o; o >>= 1) {
                            unsigned long long x = __shfl_down_sync(0xffffffffu, best, o);
                            if (x < best) best = x;
                        }
                        best = __shfl_sync(0xffffffffu, best, 0);
                        int j = (int)(unsigned)best;
                        if (t == 0) { keep_s[r] = j; ioumax[j] = 3.4e38f; }
                        __syncwarp();
                    }
                }
                __syncthreads();

                if (t < KK) g_kConf[bb][t] = sconf[keep_s[t]];
                if (t < KK * 4) {
                    int k = t >> 2, c = t & 3;
                    g_kLoc[bb][k][c] = g_sLoc[bb][keep_s[k]][c];
                }
                for (int q = t; q < KK * DM; q += 256) {
                    int k = q >> 5, d = q & (DM - 1);
                    int oi = g_sIdx[bb][keep_s[k]];
                    g_kMask[bb][k][d] = mask[((size_t)bb * PP + oi) * DM + d];
                }
                __syncthreads();

                for (int k = w; k < KK; k += 8) {
                    int i2 = keep_s[k];
                    float s = 0.f;
                    for (int j = i2 + 1 + l; j < NN; j += 32) s += g_iou[bb][i2][j] * sconf[j];
#pragma unroll
                    for (int o = 16; o; o >>= 1) s += __shfl_down_sync(0xffffffffu, s, o);
                    if (l == 0) rs_s[k] = s;
                }
                __syncthreads();

                if (t < KK) {
                    int i2 = keep_s[t];
                    float al = 0.f;
#pragma unroll
                    for (int c = 0; c < 4; c++) {
                        float v = g_kLoc[bb][t][c];
                        al += v * v;
                    }
                    al *= 0.25f;
                    aepart[t] = al * sconf[i2] * rs_s[t];
                }
                __syncthreads();
                if (t == 0) {
                    double s = 0.0;
                    for (int k = 0; k < KK; k++) s += (double)aepart[k];
                    atomicAdd(&g_accum[1], s);
                }
                __syncthreads();
            }
            __threadfence();
            if (t == 0) atomicExch(&g_ready, 1);
        }
    }

    // ================= wait: keep done (pure volatile-load spin) =================
    if (t == 0) {
        while (*((volatile int*)&g_ready) == 0) { }
    }
    __syncthreads();
    __threadfence();

    // ================= phase 2: fconf over both batches =================
    for (int q = t; q < BB * KK * DM; q += 256) {
        int bb = q / (KK * DM), rem = q % (KK * DM);
        sm_mask[bb][rem >> 5][rem & 31] = g_kMask[bb][rem >> 5][rem & 31];
    }
    if (t < BB * KK) {
        int bb = t / KK, k = t % KK;
        s_cx[bb][k] = g_kLoc[bb][k][0];
        s_cy[bb][k] = g_kLoc[bb][k][1];
        s_iw[bb][k] = 1.f / (g_kLoc[bb][k][2] + 1e-4f);
        s_ih[bb][k] = 1.f / (g_kLoc[bb][k][3] + 1e-4f);
        s_cf[bb][k] = g_kConf[bb][k];
    }
    __syncthreads();

    {
        int idx = bid * 256 + t;
        if (idx < FPIX) {
            int b = idx / (HP * WP);
            int pix = idx - b * (HP * WP);
            int y = pix / WP, x = pix - y * WP;

            const float4* pp = (const float4*)(proto + ((size_t)b * HP * WP + pix) * DM);
            float pr[DM];
#pragma unroll
            for (int q = 0; q < DM / 4; q++) {
                float4 v = pp[q];
                pr[4 * q] = v.x; pr[4 * q + 1] = v.y; pr[4 * q + 2] = v.z; pr[4 * q + 3] = v.w;
            }
            float px_ = (x + 0.5f) / (float)WP, py_ = (y + 0.5f) / (float)HP;
            float s1 = 0.f, s2 = 0.f;
#pragma unroll 2
            for (int k = 0; k < KK; k++) {
                const float4* mk = (const float4*)sm_mask[b][k];
                float d0 = 0.f, d1 = 0.f, d2 = 0.f, d3 = 0.f;
#pragma unroll
                for (int q = 0; q < DM / 4; q++) {
                    float4 mv = mk[q];
                    d0 = fmaf(pr[4 * q], mv.x, d0);
                    d1 = fmaf(pr[4 * q + 1], mv.y, d1);
                    d2 = fmaf(pr[4 * q + 2], mv.z, d2);
                    d3 = fmaf(pr[4 * q + 3], mv.w, d3);
                }
                float dot = (d0 + d1) + (d2 + d3);
                float a = __fdividef(1.f, 1.f + __expf(-dot));
                float dx = (px_ - s_cx[b][k]) * s_iw[b][k];
                float dy = (py_ - s_cy[b][k]) * s_ih[b][k];
                float ug = __expf(-0.5f * fmaf(dx, dx, dy * dy));
                float mc = a * ug * s_cf[b][k];
                s1 += mc;
                s2 = fmaf(mc, mc, s2);
            }
            float fc = 1.f - __fdividef(s2, s1 + 1e-6f);
            if (isnan(fc)) fc = 0.f;
            g_fconf[b][pix] = fc;
        }
    }

    // hoist var-phase DRAM loads ABOVE the grid barrier (overlap wait with memory)
    {
        int p4 = bid * 256 + t;
        if (p4 < NPIX4) {
#pragma unroll
            for (int b2 = 0; b2 < 2; b2++)
#pragma unroll
                for (int c = 0; c < 3; c++)
                    s_ov[t][b2 * 3 + c] = ((const float4*)orig)[(size_t)(b2 * 3 + c) * NPIX4 + p4];
        }
    }

    // ================= wait: all fconf done (atomic arrive, pure spin) =================
    __syncthreads();
    if (t == 0) {
        __threadfence();
        atomicAdd(&g_fcnt, 1);
        while (*((volatile int*)&g_fcnt) < GRID) { }
    }
    __syncthreads();
    __threadfence();

    // ================= phase 3: bilinear resize + weighted variance + finalize =================
    {
        int p4 = bid * 256 + t;
        float local = 0.f;
        if (p4 < NPIX4) {
            int base = p4 * 4;
#pragma unroll
            for (int e = 0; e < 4; e++) {
                int pix = base + e;
                int h = pix / WW, ww2 = pix - h * WW;
                const float scale = (float)HP / (float)HH;
                float sx = (ww2 + 0.5f) * scale - 0.5f;
                float sy = (h + 0.5f) * scale - 0.5f;
                float fx0 = floorf(sx), fy0 = floorf(sy);
                float ax = sx - fx0, ay = sy - fy0;
                int x0 = min(max((int)fx0, 0), WP - 1);
                int x1 = min(max((int)fx0 + 1, 0), WP - 1);
                int y0 = min(max((int)fy0, 0), HP - 1);
                int y1 = min(max((int)fy0 + 1, 0), HP - 1);
                float w00 = (1.f - ax) * (1.f - ay), w01 = ax * (1.f - ay);
                float w10 = (1.f - ax) * ay, w11 = ax * ay;

                float r0 = g_fconf[0][y0 * WP + x0] * w00 + g_fconf[0][y0 * WP + x1] * w01 +
                           g_fconf[0][y1 * WP + x0] * w10 + g_fconf[0][y1 * WP + x1] * w11;
                float r1 = g_fconf[1][y0 * WP + x0] * w00 + g_fconf[1][y0 * WP + x1] * w01 +
                           g_fconf[1][y1 * WP + x0] * w10 + g_fconf[1][y1 * WP + x1] * w11;
                float total = r0 + r1;
                float invT = __fdividef(1.f, total);
                float invTe = __fdividef(1.f, total + 1e-6f);
#pragma unroll
                for (int c = 0; c < 3; c++) {
                    float o0 = ((const float*)&s_ov[t][0 * 3 + c])[e];
                    float o1 = ((const float*)&s_ov[t][1 * 3 + c])[e];
                    float wm = (o0 * r0 + o1 * r1) * invT;
                    float dd0 = o0 - wm, dd1 = o1 - wm;
                    local += (dd0 * dd0 * r0 + dd1 * dd1 * r1) * invTe;
                }
            }
        }
        float s = blockReduceSum(local, sm);
        if (t == 0) {
            atomicAdd(&g_accum[0], (double)s);
            __threadfence();
            int ticket = atomicAdd(&g_vcnt, 1);
            if (ticket == GRID - 1) {           // last block finalizes
                double v = atomicAdd(&g_accum[0], 0.0);
                double a = atomicAdd(&g_accum[1], 0.0);
                out[0] = (float)(v / (double)HP * (double)BB);
                out[1] = (float)(a / (double)(BB * NN * NN));
            }
        }
    }
}

// ---------------- launch ----------------
extern "C" void kernel_launch(void* const* d_in, const int* in_sizes, int n_in,
                              void* d_out, int out_size) {
    const float *orig = nullptr, *loc = nullptr, *conf = nullptr, *mask = nullptr, *proto = nullptr;
    for (int i = 0; i < n_in; i++) {
        switch (in_sizes[i]) {
            case BB * 3 * HH * WW:   orig  = (const float*)d_in[i]; break;
            case BB * PP * 4:        loc   = (const float*)d_in[i]; break;
            case BB * PP * 2:        conf  = (const float*)d_in[i]; break;
            case BB * PP * DM:       mask  = (const float*)d_in[i]; break;
            case BB * HP * WP * DM:  proto = (const float*)d_in[i]; break;
            default: break;
        }
    }
    if (!orig || !loc || !conf || !mask || !proto) return;

    cudaFuncSetAttribute(k_topk, cudaFuncAttributeMaxDynamicSharedMemorySize, PP * sizeof(float));

    k_topk<<<BB, 1024, PP * sizeof(float)>>>(conf, loc);
    k_mega<<<GRID, 256>>>(mask, proto, orig, (float*)d_out);
}